// round 5
// baseline (speedup 1.0000x reference)
#include <cuda_runtime.h>
#include <cstdint>

// ---------------------------------------------------------------------------
// KQEnergyBlock: B=8, N=1024, D=768, H=12, Z=64, HID=3072
//   Q = x @ Wq^T ; K = x @ Wk^T
//   Pu = exp(beta * Q K^T)  (fused epilogue, partial row sums)
//   Zinv = 1/rowsum ; AV1 = diag(Zinv)(Pu K) ; AV2 = Pu^T diag(Zinv) Q
//   out = AV1@Wq + AV2@Wk + relu(x@Wmlp^T)@Wmlp
// R5: all operands pre-rounded to tf32; fast GEMM has both operands
// k-contiguous in smem, LDS.128 fragments via k-permutation, 64x64 warp tiles.
// ---------------------------------------------------------------------------

namespace {
constexpr int Bc = 8, Nc = 1024, Dc = 768, Hc = 12, Zc = 64, HIDc = 3072;
constexpr int Mrows = Bc * Nc;  // 8192
}

__device__ float g_Q[Mrows * Dc];
__device__ float g_K[Mrows * Dc];
__device__ float g_KT[(size_t)Bc * Hc * Zc * Nc];     // [b,h][z][seq]
__device__ float g_AV1[Mrows * Dc];
__device__ float g_AV2[Mrows * Dc];
__device__ float g_attn[(size_t)Bc * Hc * Nc * Nc];   // 402 MB (tf32-rounded Pu)
__device__ float g_hid[(size_t)Mrows * HIDc];         // 100 MB
__device__ float g_Zpart[(size_t)Bc * Hc * Nc * 32];
__device__ float g_Zinv[(size_t)Bc * Hc * Nc];
// pre-rounded inputs
__device__ float g_xr[Mrows * Dc];
__device__ float g_Wqr[Dc * Dc];
__device__ float g_Wkr[Dc * Dc];
__device__ float g_Wmlpr[HIDc * Dc];
__device__ float g_WqT[Dc * Dc];
__device__ float g_WkT[Dc * Dc];
__device__ float g_WmlpT[Dc * HIDc];

enum { EPI_STORE = 0, EPI_EXPSUM = 1, EPI_RELU = 2, EPI_ADD = 3,
       EPI_ROWSCALE = 4, EPI_STORER = 5 };

__device__ __forceinline__ uint32_t f2tf32(float f) {
    uint32_t r;
    asm("cvt.rna.tf32.f32 %0, %1;" : "=r"(r) : "f"(f));
    return r;
}
__device__ __forceinline__ float rtf(float f) { return __uint_as_float(f2tf32(f)); }

__device__ __forceinline__ void cp_async16(void* smem_dst, const void* gmem_src) {
    uint32_t sa = (uint32_t)__cvta_generic_to_shared(smem_dst);
    asm volatile("cp.async.cg.shared.global [%0], [%1], 16;\n" :: "r"(sa), "l"(gmem_src));
}
__device__ __forceinline__ void cp_commit() {
    asm volatile("cp.async.commit_group;\n");
}
template <int Nw>
__device__ __forceinline__ void cp_wait() {
    asm volatile("cp.async.wait_group %0;\n" :: "n"(Nw));
}

__device__ __forceinline__ void mma_tf32(float c[4],
                                         uint32_t a0, uint32_t a1, uint32_t a2, uint32_t a3,
                                         uint32_t b0, uint32_t b1) {
    asm volatile(
        "mma.sync.aligned.m16n8k8.row.col.f32.tf32.tf32.f32 "
        "{%0,%1,%2,%3}, {%4,%5,%6,%7}, {%8,%9}, {%0,%1,%2,%3};\n"
        : "+f"(c[0]), "+f"(c[1]), "+f"(c[2]), "+f"(c[3])
        : "r"(a0), "r"(a1), "r"(a2), "r"(a3), "r"(b0), "r"(b1));
}

// ===========================================================================
// Fast GEMM: A[m][k] (lda), B[n][k] (ldb)  -- both k-contiguous, pre-rounded.
// C[m][n]. k-permuted LDS.128 fragments, no cvt in mainloop.
// ===========================================================================
template <int BM, int BN, int BK, int WM, int WN, int EPI>
__global__ __launch_bounds__((BM / WM) * (BN / WN) * 32)
void gemm_f(const float* __restrict__ Abase, const float* __restrict__ Bbase,
            float* __restrict__ Cbase,
            int M, int N, int K, int lda, int ldb, int ldc,
            long sAb, long sAh, long sBb, long sBh, long sCb, long sCh,
            int Hdiv, const float* __restrict__ betas,
            float* __restrict__ aux, long saux)
{
    constexpr int NW = (BM / WM) * (BN / WN);
    constexpr int NT = NW * 32;
    constexpr int MT = WM / 16;
    constexpr int NTI = WN / 8;
    constexpr int NST = 3;
    static_assert(BK == 16, "BK must be 16");

    __shared__ __align__(16) float As[NST][BM][BK];
    __shared__ __align__(16) float Bs[NST][BN][BK];

    const int bz = blockIdx.z;
    const int bi = bz / Hdiv;
    const int hi = bz % Hdiv;
    const float* A = Abase + bi * sAb + hi * sAh;
    const float* Bm = Bbase + bi * sBb + hi * sBh;
    float* C = Cbase + bi * sCb + hi * sCh;
    const long auxoff = (long)bz * saux;

    const int t = threadIdx.x;
    const int warp = t >> 5;
    const int lane = t & 31;
    const int group = lane >> 2;
    const int tg = lane & 3;
    const int wm = warp / (BN / WN);
    const int wn = warp % (BN / WN);
    const int m0 = blockIdx.y * BM;
    const int n0 = blockIdx.x * BN;

    const int nk = K / BK;

    auto prefetch = [&](int kt, int s) {
        const int k0 = kt * BK;
#pragma unroll
        for (int it = 0; it < (BM * BK / 4) / NT; ++it) {
            int c = t + it * NT;
            int m = c >> 2, q = c & 3;
            cp_async16(&As[s][m][q * 4], &A[(long)(m0 + m) * lda + k0 + q * 4]);
        }
#pragma unroll
        for (int it = 0; it < (BN * BK / 4) / NT; ++it) {
            int c = t + it * NT;
            int n = c >> 2, q = c & 3;
            cp_async16(&Bs[s][n][q * 4], &Bm[(long)(n0 + n) * ldb + k0 + q * 4]);
        }
        cp_commit();
    };

    float acc[MT][NTI][4];
#pragma unroll
    for (int i = 0; i < MT; i++)
#pragma unroll
        for (int j = 0; j < NTI; j++)
#pragma unroll
            for (int r = 0; r < 4; r++) acc[i][j][r] = 0.f;

    prefetch(0, 0);
    if (nk > 1) prefetch(1, 1); else cp_commit();

    for (int kt = 0; kt < nk; kt++) {
        const int s = kt % NST;
        if (kt + 2 < nk) prefetch(kt + 2, (kt + 2) % NST);
        else cp_commit();
        cp_wait<2>();
        __syncthreads();

        // One LDS.128 per fragment row/col covers all 16 k (phys k = 4*tg..4*tg+3
        // assigned across the two k8 mma steps; valid since contraction order is free).
        float4 a4[MT][2];
        float4 b4[NTI];
#pragma unroll
        for (int mt = 0; mt < MT; mt++) {
            int mr = wm * WM + mt * 16 + group;
            a4[mt][0] = *reinterpret_cast<const float4*>(&As[s][mr][tg * 4]);
            a4[mt][1] = *reinterpret_cast<const float4*>(&As[s][mr + 8][tg * 4]);
        }
#pragma unroll
        for (int nt = 0; nt < NTI; nt++) {
            int nc = wn * WN + nt * 8 + group;
            b4[nt] = *reinterpret_cast<const float4*>(&Bs[s][nc][tg * 4]);
        }
#pragma unroll
        for (int mt = 0; mt < MT; mt++)
#pragma unroll
            for (int nt = 0; nt < NTI; nt++)
                mma_tf32(acc[mt][nt],
                         __float_as_uint(a4[mt][0].x), __float_as_uint(a4[mt][1].x),
                         __float_as_uint(a4[mt][0].y), __float_as_uint(a4[mt][1].y),
                         __float_as_uint(b4[nt].x),    __float_as_uint(b4[nt].y));
#pragma unroll
        for (int mt = 0; mt < MT; mt++)
#pragma unroll
            for (int nt = 0; nt < NTI; nt++)
                mma_tf32(acc[mt][nt],
                         __float_as_uint(a4[mt][0].z), __float_as_uint(a4[mt][1].z),
                         __float_as_uint(a4[mt][0].w), __float_as_uint(a4[mt][1].w),
                         __float_as_uint(b4[nt].z),    __float_as_uint(b4[nt].w));
        __syncthreads();
    }

    // ------------- epilogue -------------
    if (EPI == EPI_EXPSUM) {
        const float scale = betas[hi];
        const int nslot = N / WN;
#pragma unroll
        for (int mt = 0; mt < MT; mt++) {
#pragma unroll
            for (int half = 0; half < 2; half++) {
                float rsum = 0.f;
                int row = m0 + wm * WM + mt * 16 + half * 8 + group;
#pragma unroll
                for (int nt = 0; nt < NTI; nt++) {
                    int gn = n0 + wn * WN + nt * 8 + tg * 2;
                    float v0 = __expf(scale * acc[mt][nt][half * 2 + 0]);
                    float v1 = __expf(scale * acc[mt][nt][half * 2 + 1]);
                    rsum += v0 + v1;
                    float2 w; w.x = rtf(v0); w.y = rtf(v1);
                    *reinterpret_cast<float2*>(&C[(long)row * ldc + gn]) = w;
                }
                rsum += __shfl_xor_sync(0xffffffffu, rsum, 1);
                rsum += __shfl_xor_sync(0xffffffffu, rsum, 2);
                if (tg == 0)
                    aux[auxoff + (long)row * nslot + n0 / WN + wn] = rsum;
            }
        }
        return;
    }

#pragma unroll
    for (int mt = 0; mt < MT; mt++) {
#pragma unroll
        for (int nt = 0; nt < NTI; nt++) {
            int gm = m0 + wm * WM + mt * 16 + group;
            int gn = n0 + wn * WN + nt * 8 + tg * 2;
#pragma unroll
            for (int half = 0; half < 2; half++) {
                int row = gm + half * 8;
                float v0 = acc[mt][nt][half * 2 + 0];
                float v1 = acc[mt][nt][half * 2 + 1];
                if (EPI == EPI_ROWSCALE) {
                    float zi = aux[auxoff + row];
                    v0 = rtf(v0 * zi); v1 = rtf(v1 * zi);
                }
                if (EPI == EPI_RELU)   { v0 = rtf(fmaxf(v0, 0.f)); v1 = rtf(fmaxf(v1, 0.f)); }
                if (EPI == EPI_STORER) { v0 = rtf(v0); v1 = rtf(v1); }
                float2* p = reinterpret_cast<float2*>(&C[(long)row * ldc + gn]);
                if (EPI == EPI_ADD) {
                    float2 old = *p;
                    p->x = old.x + v0;
                    p->y = old.y + v1;
                } else {
                    float2 w; w.x = v0; w.y = v1;
                    *p = w;
                }
            }
        }
    }
}

// ===========================================================================
// Old-style GEMM (kept only for AV2: A = attn^T, transposed access) --
//  A logical MxK with TA=1 (A[k*lda+m]), B logical KxN TB=0 (B[k*ldb+n]).
//  FIXA: scale A by aux[k] (Zinv) at fragment load. Stores tf32-rounded.
// ===========================================================================
template <int BM, int BN, int BK, int WM, int WN>
__global__ __launch_bounds__((BM / WM) * (BN / WN) * 32)
void gemm_av2(const float* __restrict__ Abase, const float* __restrict__ Bbase,
              float* __restrict__ Cbase,
              int M, int N, int K, int lda, int ldb, int ldc,
              long sAb, long sAh, long sBb, long sBh, long sCb, long sCh,
              int Hdiv, const float* __restrict__ aux, long saux)
{
    constexpr int NW = (BM / WM) * (BN / WN);
    constexpr int NT = NW * 32;
    constexpr int MT = WM / 16;
    constexpr int NTI = WN / 8;
    constexpr int NST = 3;

    __shared__ __align__(16) float As[NST][BK][BM + 8];
    __shared__ __align__(16) float Bs[NST][BK][BN + 8];

    const int bz = blockIdx.z;
    const int bi = bz / Hdiv;
    const int hi = bz % Hdiv;
    const float* A = Abase + bi * sAb + hi * sAh;
    const float* Bm = Bbase + bi * sBb + hi * sBh;
    float* C = Cbase + bi * sCb + hi * sCh;
    const long auxoff = (long)bz * saux;

    const int t = threadIdx.x;
    const int warp = t >> 5;
    const int lane = t & 31;
    const int group = lane >> 2;
    const int tg = lane & 3;
    const int wm = warp / (BN / WN);
    const int wn = warp % (BN / WN);
    const int m0 = blockIdx.y * BM;
    const int n0 = blockIdx.x * BN;

    const int nk = K / BK;

    auto prefetch = [&](int kt, int s) {
        const int k0 = kt * BK;
#pragma unroll
        for (int it = 0; it < (BM * BK / 4) / NT; ++it) {
            int c = t + it * NT;
            int k = c / (BM / 4), mq = c % (BM / 4);
            cp_async16(&As[s][k][mq * 4], &A[(long)(k0 + k) * lda + m0 + mq * 4]);
        }
#pragma unroll
        for (int it = 0; it < (BN * BK / 4) / NT; ++it) {
            int c = t + it * NT;
            int k = c / (BN / 4), nq = c % (BN / 4);
            cp_async16(&Bs[s][k][nq * 4], &Bm[(long)(k0 + k) * ldb + n0 + nq * 4]);
        }
        cp_commit();
    };

    float acc[MT][NTI][4];
#pragma unroll
    for (int i = 0; i < MT; i++)
#pragma unroll
        for (int j = 0; j < NTI; j++)
#pragma unroll
            for (int r = 0; r < 4; r++) acc[i][j][r] = 0.f;

    prefetch(0, 0);
    if (nk > 1) prefetch(1, 1); else cp_commit();

    for (int kt = 0; kt < nk; kt++) {
        const int s = kt % NST;
        if (kt + 2 < nk) prefetch(kt + 2, (kt + 2) % NST);
        else cp_commit();
        cp_wait<2>();
        __syncthreads();
        const int k0 = kt * BK;

#pragma unroll
        for (int kk = 0; kk < BK; kk += 8) {
            uint32_t af[MT][4], bf[NTI][2];
            float z0 = aux[auxoff + k0 + kk + tg];
            float z1 = aux[auxoff + k0 + kk + tg + 4];
#pragma unroll
            for (int mt = 0; mt < MT; mt++) {
                int mr = wm * WM + mt * 16 + group;
                af[mt][0] = f2tf32(As[s][kk + tg][mr] * z0);
                af[mt][1] = f2tf32(As[s][kk + tg][mr + 8] * z0);
                af[mt][2] = f2tf32(As[s][kk + tg + 4][mr] * z1);
                af[mt][3] = f2tf32(As[s][kk + tg + 4][mr + 8] * z1);
            }
#pragma unroll
            for (int nt = 0; nt < NTI; nt++) {
                int nc = wn * WN + nt * 8 + group;
                bf[nt][0] = __float_as_uint(Bs[s][kk + tg][nc]);
                bf[nt][1] = __float_as_uint(Bs[s][kk + tg + 4][nc]);
            }
#pragma unroll
            for (int mt = 0; mt < MT; mt++)
#pragma unroll
                for (int nt = 0; nt < NTI; nt++)
                    mma_tf32(acc[mt][nt], af[mt][0], af[mt][1], af[mt][2], af[mt][3],
                             bf[nt][0], bf[nt][1]);
        }
        __syncthreads();
    }

#pragma unroll
    for (int mt = 0; mt < MT; mt++) {
#pragma unroll
        for (int nt = 0; nt < NTI; nt++) {
            int gm = m0 + wm * WM + mt * 16 + group;
            int gn = n0 + wn * WN + nt * 8 + tg * 2;
#pragma unroll
            for (int half = 0; half < 2; half++) {
                int row = gm + half * 8;
                float2 w;
                w.x = rtf(acc[mt][nt][half * 2 + 0]);
                w.y = rtf(acc[mt][nt][half * 2 + 1]);
                *reinterpret_cast<float2*>(&C[(long)row * ldc + gn]) = w;
            }
        }
    }
}

// ===========================================================================
// Pre-pass kernels
// ===========================================================================
__global__ __launch_bounds__(256) void roundcpy_k(const float* __restrict__ src,
                                                  float* __restrict__ dst, long n4)
{
    long i = (long)blockIdx.x * 256 + threadIdx.x;
    if (i >= n4) return;
    float4 v = reinterpret_cast<const float4*>(src)[i];
    v.x = rtf(v.x); v.y = rtf(v.y); v.z = rtf(v.z); v.w = rtf(v.w);
    reinterpret_cast<float4*>(dst)[i] = v;
}

// dst[C][R] = round(src[R][C]); R, C multiples of 32
__global__ __launch_bounds__(256) void trans_k(const float* __restrict__ src,
                                               float* __restrict__ dst, int R, int C)
{
    __shared__ float tile[32][33];
    int c0 = blockIdx.x * 32, r0 = blockIdx.y * 32;
    int tx = threadIdx.x & 31, ty = threadIdx.x >> 5;
    for (int i = ty; i < 32; i += 8)
        tile[i][tx] = src[(long)(r0 + i) * C + c0 + tx];
    __syncthreads();
    for (int i = ty; i < 32; i += 8)
        dst[(long)(c0 + i) * R + r0 + tx] = rtf(tile[tx][i]);
}

// KT[b,h][z][s] = K[b, s, h*64+z]   (K already rounded)
__global__ __launch_bounds__(256) void ktrans_k(const float* __restrict__ K,
                                                float* __restrict__ KT)
{
    __shared__ float tile[32][33];
    int s0 = blockIdx.x * 32, z0 = blockIdx.y * 32, bh = blockIdx.z;
    int b = bh / Hc, h = bh % Hc;
    int tx = threadIdx.x & 31, ty = threadIdx.x >> 5;
    const float* src = K + (long)b * Nc * Dc + h * Zc;
    for (int i = ty; i < 32; i += 8)
        tile[i][tx] = src[(long)(s0 + i) * Dc + z0 + tx];
    __syncthreads();
    float* dst = KT + (long)bh * Zc * Nc;
    for (int i = ty; i < 32; i += 8)
        dst[(long)(z0 + i) * Nc + s0 + tx] = tile[tx][i];
}

// Zinv = 1 / sum of 16 partials per row
__global__ __launch_bounds__(256) void zcombine_k(const float* __restrict__ part,
                                                  float* __restrict__ zinv)
{
    long i = (long)blockIdx.x * 256 + threadIdx.x;
    const float4* p = reinterpret_cast<const float4*>(part + i * 16);
    float s = 0.f;
#pragma unroll
    for (int j = 0; j < 4; j++) {
        float4 v = p[j];
        s += v.x + v.y + v.z + v.w;
    }
    zinv[i] = 1.f / s;
}

// ===========================================================================
template <int BM, int BN, int BK, int WM, int WN, int EPI>
static void run_f(const float* A, const float* B, float* C,
                  int M, int N, int K, int lda, int ldb, int ldc,
                  long sAb, long sAh, long sBb, long sBh, long sCb, long sCh,
                  int batches, int Hdiv, const float* betas,
                  float* aux = nullptr, long saux = 0)
{
    dim3 grid(N / BN, M / BM, batches);
    gemm_f<BM, BN, BK, WM, WN, EPI>
        <<<grid, (BM / WM) * (BN / WN) * 32>>>(A, B, C, M, N, K, lda, ldb, ldc,
                                               sAb, sAh, sBb, sBh, sCb, sCh,
                                               Hdiv, betas, aux, saux);
}

extern "C" void kernel_launch(void* const* d_in, const int* in_sizes, int n_in,
                              void* d_out, int out_size)
{
    const float* x     = (const float*)d_in[0];
    const float* Wq    = (const float*)d_in[1];
    const float* Wk    = (const float*)d_in[2];
    const float* betas = (const float*)d_in[3];
    const float* Wmlp  = (const float*)d_in[4];
    float* out = (float*)d_out;

    float *Q, *K, *KT, *AV1, *AV2, *attn, *hid, *Zpart, *Zinv;
    float *xr, *Wqr, *Wkr, *Wmlpr, *WqT, *WkT, *WmlpT;
    cudaGetSymbolAddress((void**)&Q,     g_Q);
    cudaGetSymbolAddress((void**)&K,     g_K);
    cudaGetSymbolAddress((void**)&KT,    g_KT);
    cudaGetSymbolAddress((void**)&AV1,   g_AV1);
    cudaGetSymbolAddress((void**)&AV2,   g_AV2);
    cudaGetSymbolAddress((void**)&attn,  g_attn);
    cudaGetSymbolAddress((void**)&hid,   g_hid);
    cudaGetSymbolAddress((void**)&Zpart, g_Zpart);
    cudaGetSymbolAddress((void**)&Zinv,  g_Zinv);
    cudaGetSymbolAddress((void**)&xr,    g_xr);
    cudaGetSymbolAddress((void**)&Wqr,   g_Wqr);
    cudaGetSymbolAddress((void**)&Wkr,   g_Wkr);
    cudaGetSymbolAddress((void**)&Wmlpr, g_Wmlpr);
    cudaGetSymbolAddress((void**)&WqT,   g_WqT);
    cudaGetSymbolAddress((void**)&WkT,   g_WkT);
    cudaGetSymbolAddress((void**)&WmlpT, g_WmlpT);

    const long ND = (long)Nc * Dc;
    const long NN = (long)Nc * Nc;

    // --- pre-round inputs / pre-transpose weights (tf32) ---
    roundcpy_k<<<(Mrows * Dc / 4 + 255) / 256, 256>>>(x, xr, Mrows * Dc / 4);
    roundcpy_k<<<(Dc * Dc / 4 + 255) / 256, 256>>>(Wq, Wqr, Dc * Dc / 4);
    roundcpy_k<<<(Dc * Dc / 4 + 255) / 256, 256>>>(Wk, Wkr, Dc * Dc / 4);
    roundcpy_k<<<(HIDc * Dc / 4 + 255) / 256, 256>>>(Wmlp, Wmlpr, HIDc * Dc / 4);
    trans_k<<<dim3(Dc / 32, Dc / 32), 256>>>(Wq, WqT, Dc, Dc);
    trans_k<<<dim3(Dc / 32, Dc / 32), 256>>>(Wk, WkT, Dc, Dc);
    trans_k<<<dim3(Dc / 32, HIDc / 32), 256>>>(Wmlp, WmlpT, HIDc, Dc);

    // 1) Q = xr @ Wqr^T ; K = xr @ Wkr^T   (B operand = W as-is: [n=e][k=d])
    run_f<128, 128, 16, 64, 64, EPI_STORER>(
        xr, Wqr, Q, Mrows, Dc, Dc, Dc, Dc, Dc, 0, 0, 0, 0, 0, 0, 1, 1, nullptr);
    run_f<128, 128, 16, 64, 64, EPI_STORER>(
        xr, Wkr, K, Mrows, Dc, Dc, Dc, Dc, Dc, 0, 0, 0, 0, 0, 0, 1, 1, nullptr);

    // KT for AV1's B operand
    ktrans_k<<<dim3(Nc / 32, Zc / 32, Bc * Hc), 256>>>(K, KT);

    // 2) Pu = exp(beta * Q K^T) rounded; partial row sums -> Zpart (16 slots/row)
    run_f<128, 128, 16, 64, 64, EPI_EXPSUM>(
        Q, K, attn, Nc, Nc, Zc, Dc, Dc, Nc,
        ND, Zc, ND, Zc, (long)Hc * NN, NN, Bc * Hc, Hc, betas,
        Zpart, (long)Nc * 16);

    // 3) Zinv
    zcombine_k<<<(Bc * Hc * Nc) / 256, 256>>>(Zpart, Zinv);

    // 4) AV1 = diag(Zinv)(Pu @ K_h): A=attn [q][k], B=KT [z][seq]
    run_f<128, 64, 16, 64, 32, EPI_ROWSCALE>(
        attn, KT, AV1, Nc, Zc, Nc, Nc, Nc, Dc,
        (long)Hc * NN, NN, (long)Hc * Zc * Nc, (long)Zc * Nc, ND, Zc,
        Bc * Hc, Hc, nullptr, Zinv, (long)Nc);

    //    AV2 = Pu^T diag(Zinv) Q  (old-style kernel, transposed A access)
    gemm_av2<128, 64, 16, 64, 32><<<dim3(1, Nc / 128, Bc * Hc), 128>>>(
        attn, Q, AV2, Nc, Zc, Nc, Nc, Dc, Dc,
        (long)Hc * NN, NN, ND, Zc, ND, Zc, Hc, Zinv, (long)Nc);

    // 5) out = AV1 @ Wq + AV2 @ Wk   (B = pre-transposed weights [d][hz])
    run_f<128, 128, 16, 64, 64, EPI_STORE>(
        AV1, WqT, out, Mrows, Dc, Dc, Dc, Dc, Dc, 0, 0, 0, 0, 0, 0, 1, 1, nullptr);
    run_f<128, 128, 16, 64, 64, EPI_ADD>(
        AV2, WkT, out, Mrows, Dc, Dc, Dc, Dc, Dc, 0, 0, 0, 0, 0, 0, 1, 1, nullptr);

    // 6) hid = relu(xr @ Wmlpr^T) ; out += hid @ WmlpT^T
    run_f<128, 128, 16, 64, 64, EPI_RELU>(
        xr, Wmlpr, hid, Mrows, HIDc, Dc, Dc, Dc, HIDc, 0, 0, 0, 0, 0, 0, 1, 1, nullptr);
    run_f<128, 128, 16, 64, 64, EPI_ADD>(
        hid, WmlpT, out, Mrows, Dc, HIDc, HIDc, HIDc, Dc, 0, 0, 0, 0, 0, 0, 1, 1, nullptr);
}

// round 8
// speedup vs baseline: 1.6704x; 1.6704x over previous
#include <cuda_runtime.h>
#include <cuda_fp16.h>
#include <cstdint>

// ---------------------------------------------------------------------------
// KQEnergyBlock: B=8, N=1024, D=768, H=12, Z=64, HID=3072
//   Q = x @ Wq^T ; K = x @ Wk^T
//   Pu = exp(beta * Q K^T)  (fused epilogue, partial row sums)
//   Zinv = 1/rowsum ; AV1 = diag(Zinv)(Pu K) ; AV2 = Pu^T (diag(Zinv) Q)
//   out = AV1@Wq + AV2@Wk + relu(x@Wmlp^T)@Wmlp
// R8 = R7 with the gemm_av2h A-tile coverage bug fixed (full 128 keys).
// All GEMMs fp16 mma.sync.m16n8k16 (fp32 accum), intermediates half.
// ---------------------------------------------------------------------------

namespace {
constexpr int Bc = 8, Nc = 1024, Dc = 768, Hc = 12, Zc = 64, HIDc = 3072;
constexpr int Mrows = Bc * Nc;  // 8192
}

__device__ __align__(16) __half g_Qh[Mrows * Dc];
__device__ __align__(16) __half g_Kh[Mrows * Dc];
__device__ __align__(16) __half g_KTh[(size_t)Bc * Hc * Zc * Nc];
__device__ __align__(16) __half g_QsTh[(size_t)Bc * Hc * Zc * Nc];
__device__ __align__(16) __half g_AV1h[Mrows * Dc];
__device__ __align__(16) __half g_AV2h[Mrows * Dc];
__device__ __align__(16) __half g_attnh[(size_t)Bc * Hc * Nc * Nc];  // 201 MB
__device__ __align__(16) __half g_hidh[(size_t)Mrows * HIDc];        // 50 MB
__device__ __align__(16) float  g_Zpart[(size_t)Bc * Hc * Nc * 16];
__device__ __align__(16) float  g_Zinv[(size_t)Bc * Hc * Nc];
__device__ __align__(16) __half g_xh[Mrows * Dc];
__device__ __align__(16) __half g_Wqh[Dc * Dc];
__device__ __align__(16) __half g_Wkh[Dc * Dc];
__device__ __align__(16) __half g_Wmlph[HIDc * Dc];
__device__ __align__(16) __half g_WqTh[Dc * Dc];
__device__ __align__(16) __half g_WkTh[Dc * Dc];
__device__ __align__(16) __half g_WmlpTh[Dc * HIDc];

enum { E_STOREF = 0, E_ADDF = 1, E_STOREH = 2, E_RELUH = 3,
       E_EXPSUM = 4, E_ROWSCALEH = 5 };

__device__ __forceinline__ void cp_async16(void* smem_dst, const void* gmem_src) {
    uint32_t sa = (uint32_t)__cvta_generic_to_shared(smem_dst);
    asm volatile("cp.async.cg.shared.global [%0], [%1], 16;\n" :: "r"(sa), "l"(gmem_src));
}
__device__ __forceinline__ void cp_commit() {
    asm volatile("cp.async.commit_group;\n");
}
template <int Nw>
__device__ __forceinline__ void cp_wait() {
    asm volatile("cp.async.wait_group %0;\n" :: "n"(Nw));
}

__device__ __forceinline__ void mma_f16(float c[4],
                                        uint32_t a0, uint32_t a1, uint32_t a2, uint32_t a3,
                                        uint32_t b0, uint32_t b1) {
    asm volatile(
        "mma.sync.aligned.m16n8k16.row.col.f32.f16.f16.f32 "
        "{%0,%1,%2,%3}, {%4,%5,%6,%7}, {%8,%9}, {%0,%1,%2,%3};\n"
        : "+f"(c[0]), "+f"(c[1]), "+f"(c[2]), "+f"(c[3])
        : "r"(a0), "r"(a1), "r"(a2), "r"(a3), "r"(b0), "r"(b1));
}

// ===========================================================================
// Fast half GEMM: C = A[m][k] @ B[n][k]^T, both k-contiguous half. BK=32.
// One LDS.128 per fragment row/col covers 16 phys k (k-permutation: the
// contraction order within an mma is free as long as A and B slots agree).
// ===========================================================================
template <int BM, int BN, int WM, int WN, int EPI>
__global__ __launch_bounds__((BM / WM) * (BN / WN) * 32)
void gemm_h(const __half* __restrict__ Abase, const __half* __restrict__ Bbase,
            void* __restrict__ Cbase, int K, int lda, int ldb, int ldc,
            long sAb, long sAh, long sBb, long sBh, long sCb, long sCh,
            int Hdiv, const float* __restrict__ betas,
            float* __restrict__ auxF, const float* __restrict__ zinv, long saux)
{
    constexpr int BK = 32;
    constexpr int NW = (BM / WM) * (BN / WN);
    constexpr int NT = NW * 32;
    constexpr int MT = WM / 16;
    constexpr int NTI = WN / 8;
    constexpr int NST = 3;

    __shared__ __align__(16) __half As[NST][BM][BK];
    __shared__ __align__(16) __half Bs[NST][BN][BK];

    const int bz = blockIdx.z;
    const int bi = bz / Hdiv;
    const int hi = bz % Hdiv;
    const __half* A = Abase + bi * sAb + hi * sAh;
    const __half* Bm = Bbase + bi * sBb + hi * sBh;
    const long auxoff = (long)bz * saux;

    const int t = threadIdx.x;
    const int warp = t >> 5;
    const int lane = t & 31;
    const int group = lane >> 2;
    const int tg = lane & 3;
    const int wm = warp / (BN / WN);
    const int wn = warp % (BN / WN);
    const int m0 = blockIdx.y * BM;
    const int n0 = blockIdx.x * BN;

    const int nk = K / BK;

    auto prefetch = [&](int kt, int s) {
        const int k0 = kt * BK;
#pragma unroll
        for (int it = 0; it < (BM * 4) / NT; ++it) {
            int c = t + it * NT;
            int m = c >> 2, q = c & 3;
            cp_async16(&As[s][m][q * 8], &A[(long)(m0 + m) * lda + k0 + q * 8]);
        }
#pragma unroll
        for (int it = 0; it < (BN * 4) / NT; ++it) {
            int c = t + it * NT;
            int n = c >> 2, q = c & 3;
            cp_async16(&Bs[s][n][q * 8], &Bm[(long)(n0 + n) * ldb + k0 + q * 8]);
        }
        cp_commit();
    };

    float acc[MT][NTI][4];
#pragma unroll
    for (int i = 0; i < MT; i++)
#pragma unroll
        for (int j = 0; j < NTI; j++)
#pragma unroll
            for (int r = 0; r < 4; r++) acc[i][j][r] = 0.f;

    if (0 < nk) prefetch(0, 0); else cp_commit();
    if (1 < nk) prefetch(1, 1); else cp_commit();

    for (int kt = 0; kt < nk; kt++) {
        const int s = kt % NST;
        if (kt + 2 < nk) prefetch(kt + 2, (kt + 2) % NST);
        else cp_commit();
        cp_wait<2>();
        __syncthreads();

        uint4 a4[MT][2];
        uint4 b4[NTI];
#pragma unroll
        for (int mt = 0; mt < MT; mt++) {
            int mr = wm * WM + mt * 16 + group;
            a4[mt][0] = *reinterpret_cast<const uint4*>(&As[s][mr][tg * 8]);
            a4[mt][1] = *reinterpret_cast<const uint4*>(&As[s][mr + 8][tg * 8]);
        }
#pragma unroll
        for (int nt = 0; nt < NTI; nt++) {
            int nc = wn * WN + nt * 8 + group;
            b4[nt] = *reinterpret_cast<const uint4*>(&Bs[s][nc][tg * 8]);
        }
#pragma unroll
        for (int mt = 0; mt < MT; mt++)
#pragma unroll
            for (int nt = 0; nt < NTI; nt++)
                mma_f16(acc[mt][nt], a4[mt][0].x, a4[mt][1].x, a4[mt][0].y, a4[mt][1].y,
                        b4[nt].x, b4[nt].y);
#pragma unroll
        for (int mt = 0; mt < MT; mt++)
#pragma unroll
            for (int nt = 0; nt < NTI; nt++)
                mma_f16(acc[mt][nt], a4[mt][0].z, a4[mt][1].z, a4[mt][0].w, a4[mt][1].w,
                        b4[nt].z, b4[nt].w);
        __syncthreads();
    }

    // ---------------- epilogue ----------------
    if (EPI == E_EXPSUM) {
        __half* C = (__half*)Cbase + bi * sCb + hi * sCh;
        const float scale = betas[hi];
        const int nslot = 1024 / WN;   // N == Nc here
#pragma unroll
        for (int mt = 0; mt < MT; mt++) {
#pragma unroll
            for (int half = 0; half < 2; half++) {
                float rsum = 0.f;
                int row = m0 + wm * WM + mt * 16 + half * 8 + group;
#pragma unroll
                for (int nt = 0; nt < NTI; nt++) {
                    int gn = n0 + wn * WN + nt * 8 + tg * 2;
                    float v0 = __expf(scale * acc[mt][nt][half * 2 + 0]);
                    float v1 = __expf(scale * acc[mt][nt][half * 2 + 1]);
                    rsum += v0 + v1;
                    *reinterpret_cast<__half2*>(&C[(long)row * ldc + gn]) =
                        __floats2half2_rn(v0, v1);
                }
                rsum += __shfl_xor_sync(0xffffffffu, rsum, 1);
                rsum += __shfl_xor_sync(0xffffffffu, rsum, 2);
                if (tg == 0)
                    auxF[auxoff + (long)row * nslot + n0 / WN + wn] = rsum;
            }
        }
        return;
    }

#pragma unroll
    for (int mt = 0; mt < MT; mt++) {
#pragma unroll
        for (int nt = 0; nt < NTI; nt++) {
            int gm = m0 + wm * WM + mt * 16 + group;
            int gn = n0 + wn * WN + nt * 8 + tg * 2;
#pragma unroll
            for (int half = 0; half < 2; half++) {
                int row = gm + half * 8;
                float v0 = acc[mt][nt][half * 2 + 0];
                float v1 = acc[mt][nt][half * 2 + 1];
                if (EPI == E_ROWSCALEH) {
                    float zi = zinv[auxoff + row];
                    v0 *= zi; v1 *= zi;
                }
                if (EPI == E_RELUH) { v0 = fmaxf(v0, 0.f); v1 = fmaxf(v1, 0.f); }
                if (EPI == E_STOREF || EPI == E_ADDF) {
                    float* C = (float*)Cbase + bi * sCb + hi * sCh;
                    float2* p = reinterpret_cast<float2*>(&C[(long)row * ldc + gn]);
                    if (EPI == E_ADDF) {
                        float2 o = *p;
                        p->x = o.x + v0; p->y = o.y + v1;
                    } else {
                        float2 w; w.x = v0; w.y = v1; *p = w;
                    }
                } else {
                    __half* C = (__half*)Cbase + bi * sCb + hi * sCh;
                    *reinterpret_cast<__half2*>(&C[(long)row * ldc + gn]) =
                        __floats2half2_rn(v0, v1);
                }
            }
        }
    }
}

// ===========================================================================
// AV2 kernel: C[key, z] = sum_q Pu[q][key] * Qs[q][z]
// A = Pu read row-wise, packed pair-major:
//   As2[p][m] = half2{ Pu[q0+2p][m0+m], Pu[q0+2p+1][m0+m] }, m = 0..127 (FIXED)
// B = QsT[bh][z][q] (k=q contiguous). Reg-staged double buffer.
// BM=128 keys, BN=64 z, BK=32 q; 4 warps (warp tile 64x32).
// ===========================================================================
__global__ __launch_bounds__(128)
void gemm_av2h(const __half* __restrict__ attn, const __half* __restrict__ QsT,
               __half* __restrict__ AV2, int Hdiv)
{
    constexpr int MT = 4, NTI = 4;
    __shared__ __align__(16) uint32_t As2[2][16][136];
    __shared__ __align__(16) __half Bs[2][64][40];

    const int bz = blockIdx.z;
    const int bi = bz / Hdiv;
    const int hi = bz % Hdiv;
    const __half* A = attn + (long)bi * Hc * Nc * Nc + (long)hi * Nc * Nc;
    const __half* Bq = QsT + (long)bz * Zc * Nc;
    __half* C = AV2 + (long)bi * Nc * Dc + hi * Zc;

    const int t = threadIdx.x;
    const int warp = t >> 5;
    const int lane = t & 31;
    const int group = lane >> 2;
    const int tg = lane & 3;
    const int wm = warp >> 1;          // 0..1
    const int wn = warp & 1;           // 0..1
    const int m0 = blockIdx.y * 128;

    const int nk = Nc / 32;            // 32

    // staging regs: 4 tasks x {even,odd q-row}, 4 half columns each
    uint2 ra[4][2];
    uint4 rb[2];

    auto ldgA = [&](int kt) {
        const int q0 = kt * 32;
#pragma unroll
        for (int it = 0; it < 4; it++) {
            int c = t + it * 128;              // 0..511
            int p = c >> 5, j = c & 31;        // p: q-pair 0..15, cols 4j..4j+3
            ra[it][0] = *reinterpret_cast<const uint2*>(
                &A[(long)(q0 + 2 * p) * Nc + m0 + 4 * j]);
            ra[it][1] = *reinterpret_cast<const uint2*>(
                &A[(long)(q0 + 2 * p + 1) * Nc + m0 + 4 * j]);
        }
    };
    auto ldgB = [&](int kt) {
        const int q0 = kt * 32;
#pragma unroll
        for (int it = 0; it < 2; it++) {
            int c = t + it * 128;
            int n = c >> 2, q = c & 3;
            rb[it] = *reinterpret_cast<const uint4*>(&Bq[(long)n * Nc + q0 + q * 8]);
        }
    };
    auto stsAB = [&](int s) {
#pragma unroll
        for (int it = 0; it < 4; it++) {
            int c = t + it * 128;
            int p = c >> 5, j = c & 31;
            As2[s][p][4 * j + 0] = __byte_perm(ra[it][0].x, ra[it][1].x, 0x5410);
            As2[s][p][4 * j + 1] = __byte_perm(ra[it][0].x, ra[it][1].x, 0x7632);
            As2[s][p][4 * j + 2] = __byte_perm(ra[it][0].y, ra[it][1].y, 0x5410);
            As2[s][p][4 * j + 3] = __byte_perm(ra[it][0].y, ra[it][1].y, 0x7632);
        }
#pragma unroll
        for (int it = 0; it < 2; it++) {
            int c = t + it * 128;
            int n = c >> 2, q = c & 3;
            *reinterpret_cast<uint4*>(&Bs[s][n][q * 8]) = rb[it];
        }
    };

    float acc[MT][NTI][4];
#pragma unroll
    for (int i = 0; i < MT; i++)
#pragma unroll
        for (int j = 0; j < NTI; j++)
#pragma unroll
            for (int r = 0; r < 4; r++) acc[i][j][r] = 0.f;

    ldgA(0); ldgB(0);

    for (int kt = 0; kt < nk; kt++) {
        const int s = kt & 1;
        stsAB(s);
        __syncthreads();
        if (kt + 1 < nk) { ldgA(kt + 1); ldgB(kt + 1); }

        // two k16 steps: step0 uses q-pairs {tg, tg+4}, step1 {8+tg, 12+tg}
#pragma unroll
        for (int step = 0; step < 2; step++) {
            const int pb = step * 8;
            uint32_t af[MT][4];
            uint32_t bf[NTI][2];
#pragma unroll
            for (int mt = 0; mt < MT; mt++) {
                int mr = wm * 64 + mt * 16 + group;
                af[mt][0] = As2[s][pb + tg][mr];
                af[mt][1] = As2[s][pb + tg][mr + 8];
                af[mt][2] = As2[s][pb + tg + 4][mr];
                af[mt][3] = As2[s][pb + tg + 4][mr + 8];
            }
#pragma unroll
            for (int nt = 0; nt < NTI; nt++) {
                int nc = wn * 32 + nt * 8 + group;
                bf[nt][0] = *reinterpret_cast<const uint32_t*>(&Bs[s][nc][pb * 2 + tg * 2]);
                bf[nt][1] = *reinterpret_cast<const uint32_t*>(&Bs[s][nc][pb * 2 + 8 + tg * 2]);
            }
#pragma unroll
            for (int mt = 0; mt < MT; mt++)
#pragma unroll
                for (int nt = 0; nt < NTI; nt++)
                    mma_f16(acc[mt][nt], af[mt][0], af[mt][1], af[mt][2], af[mt][3],
                            bf[nt][0], bf[nt][1]);
        }
        __syncthreads();
    }

#pragma unroll
    for (int mt = 0; mt < MT; mt++) {
#pragma unroll
        for (int nt = 0; nt < NTI; nt++) {
            int gm = m0 + wm * 64 + mt * 16 + group;
            int gn = wn * 32 + nt * 8 + tg * 2;
#pragma unroll
            for (int half = 0; half < 2; half++) {
                int row = gm + half * 8;
                *reinterpret_cast<__half2*>(&C[(long)row * Dc + gn]) =
                    __floats2half2_rn(acc[mt][nt][half * 2 + 0],
                                      acc[mt][nt][half * 2 + 1]);
            }
        }
    }
}

// ===========================================================================
// Pre-pass kernels
// ===========================================================================
__global__ __launch_bounds__(256) void hconv_k(const float* __restrict__ src,
                                               __half* __restrict__ dst, long n4)
{
    long i = (long)blockIdx.x * 256 + threadIdx.x;
    if (i >= n4) return;
    float4 v = reinterpret_cast<const float4*>(src)[i];
    __half2 h0 = __floats2half2_rn(v.x, v.y);
    __half2 h1 = __floats2half2_rn(v.z, v.w);
    uint2 u;
    u.x = *reinterpret_cast<uint32_t*>(&h0);
    u.y = *reinterpret_cast<uint32_t*>(&h1);
    reinterpret_cast<uint2*>(dst)[i] = u;
}

// dst[C][R] = half(src[R][C]) ; float src
__global__ __launch_bounds__(256) void htrans_k(const float* __restrict__ src,
                                                __half* __restrict__ dst, int R, int C)
{
    __shared__ float tile[32][33];
    int c0 = blockIdx.x * 32, r0 = blockIdx.y * 32;
    int tx = threadIdx.x & 31, ty = threadIdx.x >> 5;
    for (int i = ty; i < 32; i += 8)
        tile[i][tx] = src[(long)(r0 + i) * C + c0 + tx];
    __syncthreads();
    for (int i = ty; i < 32; i += 8)
        dst[(long)(c0 + i) * R + r0 + tx] = __float2half(tile[tx][i]);
}

// KTh[bh][z][s] = Kh[b, s, h*64+z]
__global__ __launch_bounds__(256) void ktrans_h(const __half* __restrict__ K,
                                                __half* __restrict__ KT)
{
    __shared__ __half tile[32][33];
    int s0 = blockIdx.x * 32, z0 = blockIdx.y * 32, bh = blockIdx.z;
    int b = bh / Hc, h = bh % Hc;
    int tx = threadIdx.x & 31, ty = threadIdx.x >> 5;
    const __half* src = K + (long)b * Nc * Dc + h * Zc;
    for (int i = ty; i < 32; i += 8)
        tile[i][tx] = src[(long)(s0 + i) * Dc + z0 + tx];
    __syncthreads();
    __half* dst = KT + (long)bh * Zc * Nc;
    for (int i = ty; i < 32; i += 8)
        dst[(long)(z0 + i) * Nc + s0 + tx] = tile[tx][i];
}

// QsTh[bh][z][q] = Qh[b, q, h*64+z] * Zinv[bh][q]
__global__ __launch_bounds__(256) void qstrans_h(const __half* __restrict__ Q,
                                                 const float* __restrict__ zinv,
                                                 __half* __restrict__ QT)
{
    __shared__ __half tile[32][33];
    int s0 = blockIdx.x * 32, z0 = blockIdx.y * 32, bh = blockIdx.z;
    int b = bh / Hc, h = bh % Hc;
    int tx = threadIdx.x & 31, ty = threadIdx.x >> 5;
    const __half* src = Q + (long)b * Nc * Dc + h * Zc;
    const float* zv = zinv + (long)bh * Nc;
    for (int i = ty; i < 32; i += 8) {
        float v = __half2float(src[(long)(s0 + i) * Dc + z0 + tx]) * zv[s0 + i];
        tile[i][tx] = __float2half(v);
    }
    __syncthreads();
    __half* dst = QT + (long)bh * Zc * Nc;
    for (int i = ty; i < 32; i += 8)
        dst[(long)(z0 + i) * Nc + s0 + tx] = tile[tx][i];
}

__global__ __launch_bounds__(256) void zcombine_k(const float* __restrict__ part,
                                                  float* __restrict__ zinv)
{
    long i = (long)blockIdx.x * 256 + threadIdx.x;
    const float4* p = reinterpret_cast<const float4*>(part + i * 16);
    float s = 0.f;
#pragma unroll
    for (int j = 0; j < 4; j++) {
        float4 v = p[j];
        s += v.x + v.y + v.z + v.w;
    }
    zinv[i] = 1.f / s;
}

// ===========================================================================
template <int BM, int BN, int WM, int WN, int EPI>
static void run_h(const __half* A, const __half* B, void* C,
                  int M, int N, int K, int lda, int ldb, int ldc,
                  long sAb, long sAh, long sBb, long sBh, long sCb, long sCh,
                  int batches, int Hdiv, const float* betas,
                  float* auxF = nullptr, const float* zinv = nullptr, long saux = 0)
{
    dim3 grid(N / BN, M / BM, batches);
    gemm_h<BM, BN, WM, WN, EPI>
        <<<grid, (BM / WM) * (BN / WN) * 32>>>(A, B, C, K, lda, ldb, ldc,
                                               sAb, sAh, sBb, sBh, sCb, sCh,
                                               Hdiv, betas, auxF, zinv, saux);
}

extern "C" void kernel_launch(void* const* d_in, const int* in_sizes, int n_in,
                              void* d_out, int out_size)
{
    const float* x     = (const float*)d_in[0];
    const float* Wq    = (const float*)d_in[1];
    const float* Wk    = (const float*)d_in[2];
    const float* betas = (const float*)d_in[3];
    const float* Wmlp  = (const float*)d_in[4];
    float* out = (float*)d_out;

    __half *Qh, *Kh, *KTh, *QsTh, *AV1h, *AV2h, *attnh, *hidh;
    __half *xh, *Wqh, *Wkh, *Wmlph, *WqTh, *WkTh, *WmlpTh;
    float *Zpart, *Zinv;
    cudaGetSymbolAddress((void**)&Qh,     g_Qh);
    cudaGetSymbolAddress((void**)&Kh,     g_Kh);
    cudaGetSymbolAddress((void**)&KTh,    g_KTh);
    cudaGetSymbolAddress((void**)&QsTh,   g_QsTh);
    cudaGetSymbolAddress((void**)&AV1h,   g_AV1h);
    cudaGetSymbolAddress((void**)&AV2h,   g_AV2h);
    cudaGetSymbolAddress((void**)&attnh,  g_attnh);
    cudaGetSymbolAddress((void**)&hidh,   g_hidh);
    cudaGetSymbolAddress((void**)&Zpart,  g_Zpart);
    cudaGetSymbolAddress((void**)&Zinv,   g_Zinv);
    cudaGetSymbolAddress((void**)&xh,     g_xh);
    cudaGetSymbolAddress((void**)&Wqh,    g_Wqh);
    cudaGetSymbolAddress((void**)&Wkh,    g_Wkh);
    cudaGetSymbolAddress((void**)&Wmlph,  g_Wmlph);
    cudaGetSymbolAddress((void**)&WqTh,   g_WqTh);
    cudaGetSymbolAddress((void**)&WkTh,   g_WkTh);
    cudaGetSymbolAddress((void**)&WmlpTh, g_WmlpTh);

    const long ND = (long)Nc * Dc;
    const long NN = (long)Nc * Nc;
    const long ZN = (long)Zc * Nc;

    // ---- convert inputs to half; build transposed weights ----
    hconv_k<<<(Mrows * Dc / 4 + 255) / 256, 256>>>(x, xh, Mrows * Dc / 4);
    hconv_k<<<(Dc * Dc / 4 + 255) / 256, 256>>>(Wq, Wqh, Dc * Dc / 4);
    hconv_k<<<(Dc * Dc / 4 + 255) / 256, 256>>>(Wk, Wkh, Dc * Dc / 4);
    hconv_k<<<(HIDc * Dc / 4 + 255) / 256, 256>>>(Wmlp, Wmlph, HIDc * Dc / 4);
    htrans_k<<<dim3(Dc / 32, Dc / 32), 256>>>(Wq, WqTh, Dc, Dc);
    htrans_k<<<dim3(Dc / 32, Dc / 32), 256>>>(Wk, WkTh, Dc, Dc);
    htrans_k<<<dim3(Dc / 32, HIDc / 32), 256>>>(Wmlp, WmlpTh, HIDc, Dc);

    // 1) Q = x @ Wq^T ; K = x @ Wk^T
    run_h<128, 128, 64, 64, E_STOREH>(
        xh, Wqh, Qh, Mrows, Dc, Dc, Dc, Dc, Dc, 0, 0, 0, 0, 0, 0, 1, 1, nullptr);
    run_h<128, 128, 64, 64, E_STOREH>(
        xh, Wkh, Kh, Mrows, Dc, Dc, Dc, Dc, Dc, 0, 0, 0, 0, 0, 0, 1, 1, nullptr);

    ktrans_h<<<dim3(Nc / 32, Zc / 32, Bc * Hc), 256>>>(Kh, KTh);

    // 2) Pu = exp(beta * Q K^T); partial row sums -> Zpart (16 slots/row)
    run_h<128, 128, 64, 64, E_EXPSUM>(
        Qh, Kh, attnh, Nc, Nc, Zc, Dc, Dc, Nc,
        ND, Zc, ND, Zc, (long)Hc * NN, NN, Bc * Hc, Hc, betas,
        Zpart, nullptr, (long)Nc * 16);

    zcombine_k<<<(Bc * Hc * Nc) / 256, 256>>>(Zpart, Zinv);

    // Qs = diag(Zinv) Q, transposed per head
    qstrans_h<<<dim3(Nc / 32, Zc / 32, Bc * Hc), 256>>>(Qh, Zinv, QsTh);

    // 3) AV1 = diag(Zinv)(Pu @ K) ; AV2 = Pu^T @ Qs
    run_h<128, 64, 64, 32, E_ROWSCALEH>(
        attnh, KTh, AV1h, Nc, Zc, Nc, Nc, Nc, Dc,
        (long)Hc * NN, NN, (long)Hc * ZN, ZN, ND, Zc,
        Bc * Hc, Hc, nullptr, nullptr, Zinv, (long)Nc);
    gemm_av2h<<<dim3(1, Nc / 128, Bc * Hc), 128>>>(attnh, QsTh, AV2h, Hc);

    // 4) out = AV1 @ Wq ; out += AV2 @ Wk
    run_h<128, 128, 64, 64, E_STOREF>(
        AV1h, WqTh, out, Mrows, Dc, Dc, Dc, Dc, Dc, 0, 0, 0, 0, 0, 0, 1, 1, nullptr);
    run_h<128, 128, 64, 64, E_ADDF>(
        AV2h, WkTh, out, Mrows, Dc, Dc, Dc, Dc, Dc, 0, 0, 0, 0, 0, 0, 1, 1, nullptr);

    // 5) hid = relu(x @ Wmlp^T) ; out += hid @ WmlpT^T
    run_h<128, 128, 64, 64, E_RELUH>(
        xh, Wmlph, hidh, Mrows, HIDc, Dc, Dc, Dc, HIDc, 0, 0, 0, 0, 0, 0, 1, 1, nullptr);
    run_h<128, 128, 64, 64, E_ADDF>(
        hidh, WmlpTh, out, Mrows, Dc, HIDc, HIDc, HIDc, Dc, 0, 0, 0, 0, 0, 0, 1, 1, nullptr);
}